// round 3
// baseline (speedup 1.0000x reference)
#include <cuda_runtime.h>

#define BDIM   256
#define TQ     900
#define TK     200
#define BATCH  128
#define NEG    (-1e30f)
#define LOG2E  1.4426950408889634f
#define LN2    0.6931471805599453f
#define TB     32           // time-block per wavefront pass
#define PPW    26           // state-pairs per warp (8*26 = 208 >= 201)

__device__ float g_losses[BATCH];

__device__ __forceinline__ float ex2f(float x) {
    float y; asm("ex2.approx.ftz.f32 %0, %1;" : "=f"(y) : "f"(x)); return y;
}
__device__ __forceinline__ float lg2f(float x) {
    float y; asm("lg2.approx.ftz.f32 %0, %1;" : "=f"(y) : "f"(x)); return y;
}
// log2-domain logaddexp
__device__ __forceinline__ float lse2(float x, float y) {
    float m = fmaxf(x, y);
    return m + lg2f(1.0f + ex2f(-fabsf(x - y)));
}

// One CTA per batch element. 8 warps; warp w owns pairs j = 26w+lane (lane<26).
// Wavefront over time: warp w processes time-block (p - w) in pass p; the only
// cross-warp value (odd alpha of each warp's last pair) goes through s_bnd,
// made visible by one barrier per pass (~36 barriers total instead of ~800).
__global__ __launch_bounds__(BDIM, 1)
void ctc_kernel(const float* __restrict__ attn,
                const int*   __restrict__ in_lens,
                const int*   __restrict__ out_lens)
{
    __shared__ float s_dn[TQ];        // log2-domain softmax denominators
    __shared__ float s_bnd[7][TQ];    // boundary odd alphas (warp w -> warp w+1)
    __shared__ float s_hi, s_lo;

    const int b    = blockIdx.x;
    const int tid  = threadIdx.x;
    const int lane = tid & 31;
    const int w    = tid >> 5;
    const int L       = in_lens[b];    // 100..200
    const int out_len = out_lens[b];   // 700..900
    const float* attn_b = attn + (size_t)b * TQ * TK;

    const int  j      = w * PPW + lane;              // state-pair index
    const bool active = (lane < PPW) && (j <= 200);
    const bool loadok = (lane < PPW) && (j < 200);   // odd emit exists for j<200

    // ---------------- Phase 1: denominators for all rows t < out_len -------
    for (int t = w; t < out_len; t += 8) {
        const float* row = attn_b + (size_t)t * TK;
        float v[7];
        float m = -1.0f;                      // blank logit included in max
        #pragma unroll
        for (int i = 0; i < 7; ++i) {
            int k = lane + 32 * i;
            v[i] = (k < TK) ? __ldg(row + k) : NEG;
            m = fmaxf(m, v[i]);
        }
        #pragma unroll
        for (int off = 16; off; off >>= 1)
            m = fmaxf(m, __shfl_xor_sync(0xffffffffu, m, off));
        float s = 0.f;
        #pragma unroll
        for (int i = 0; i < 7; ++i) s += ex2f((v[i] - m) * LOG2E);
        #pragma unroll
        for (int off = 16; off; off >>= 1)
            s += __shfl_xor_sync(0xffffffffu, s, off);
        s += ex2f((-1.0f - m) * LOG2E);       // blank term
        if (lane == 0) s_dn[t] = m * LOG2E + lg2f(s);
    }

    // ---------------- Phase 2: wavefront DP --------------------------------
    const int nblocks = (out_len + TB - 1) / TB;

    float a_e = NEG, a_o = NEG;
    float xv[TB], xn[TB], bndv[TB];

    // Warp 0 pre-loads its block 0 (other warps prefetch at pass bb-1 == -1).
    if (w == 0) {
        #pragma unroll
        for (int k = 0; k < TB; ++k)
            xn[k] = (loadok && k < out_len) ? __ldg(attn_b + (size_t)k * TK + j) : 0.f;
    }

    const int npass = nblocks + 7;
    for (int p = 0; p < npass; ++p) {
        __syncthreads();                       // all threads, every pass
        const int bb = p - w;

        if (bb == -1) {
            // prefetch this warp's block 0 for next pass
            #pragma unroll
            for (int k = 0; k < TB; ++k)
                xn[k] = (loadok && k < out_len) ? __ldg(attn_b + (size_t)k * TK + j) : 0.f;
        } else if (bb >= 0 && bb < nblocks) {
            const int t0 = bb * TB;

            #pragma unroll
            for (int k = 0; k < TB; ++k) xv[k] = xn[k];

            // prefetch next block's emit values (consumed next pass)
            if (bb + 1 < nblocks) {
                #pragma unroll
                for (int k = 0; k < TB; ++k) {
                    int t = t0 + TB + k;
                    xn[k] = (loadok && t < out_len) ? __ldg(attn_b + (size_t)t * TK + j) : 0.f;
                }
            }
            // prefetch boundary values (written by warp w-1 in earlier passes)
            #pragma unroll
            for (int k = 0; k < TB; ++k) {
                int idx = t0 + k - 1; if (idx < 0) idx = 0;
                bndv[k] = (w > 0) ? s_bnd[w - 1][idx] : NEG;
            }

            #pragma unroll
            for (int k = 0; k < TB; ++k) {
                const int t = t0 + k;
                if (t < out_len) {
                    const float dn = s_dn[t];
                    const float cE = -LOG2E - dn;        // blank emit (log2)
                    float a1 = __shfl_up_sync(0xffffffffu, a_o, 1);
                    if (lane == 0) a1 = (w > 0) ? bndv[k] : NEG;
                    const float pre = lse2(a_o, a_e);    // off critical chain

                    float ne, no;
                    if (bb == 0 && k == 0) {
                        // t == 0 initialization (all warps; only j==0 non-NEG)
                        ne = (j == 0) ? cE : NEG;
                        no = (j == 0) ? (xv[0] * LOG2E - dn) : NEG;
                    } else {
                        ne = lse2(a_e, a1) + cE;
                        const float emit = (j < L) ? (xv[k] * LOG2E - dn) : 0.f;
                        no = lse2(pre, a1) + emit;
                    }
                    if (lane == PPW - 1 && w < 7) s_bnd[w][t] = no;
                    a_e = ne; a_o = no;
                }
            }
        }
    }

    // ---------------- Extraction ------------------------------------------
    __syncthreads();
    if (active && j == L)     s_hi = a_e;   // fin[2L]
    if (active && j == L - 1) s_lo = a_o;   // fin[2L-1]
    __syncthreads();
    if (tid == 0) {
        float hi = s_hi, lo = s_lo;
        float M  = fmaxf(hi, lo);
        float l2 = M + lg2f(ex2f(hi - M) + ex2f(lo - M));
        float loss = -l2 * LN2;
        if (loss > 1e20f) loss = 0.0f;
        g_losses[b] = loss / (float)L;
    }
}

// Deterministic mean over the 128 per-batch losses.
__global__ void reduce_kernel(float* __restrict__ out)
{
    __shared__ float sb[BATCH];
    sb[threadIdx.x] = g_losses[threadIdx.x];
    __syncthreads();
    if (threadIdx.x == 0) {
        float s = 0.f;
        for (int i = 0; i < BATCH; ++i) s += sb[i];
        out[0] = s * (1.0f / BATCH);
    }
}

extern "C" void kernel_launch(void* const* d_in, const int* in_sizes, int n_in,
                              void* d_out, int out_size)
{
    const float* attn     = (const float*)d_in[0];
    const int*   in_lens  = (const int*)d_in[1];
    const int*   out_lens = (const int*)d_in[2];
    (void)in_sizes; (void)n_in; (void)out_size;

    ctc_kernel<<<BATCH, BDIM>>>(attn, in_lens, out_lens);
    reduce_kernel<<<1, BATCH>>>((float*)d_out);
}

// round 4
// speedup vs baseline: 1.0628x; 1.0628x over previous
#include <cuda_runtime.h>

#define TQ      900
#define TK      200
#define BATCH   128
#define NEG     (-1e30f)
#define LOG2E   1.4426950408889634f
#define LN2     0.6931471805599453f
#define CHUNK   8
#define NDP     256          // 8 DP warps
#define NPROD   128          // 4 producer warps
#define NTHREADS 384

// named barrier ids
#define BAR_STEP      1              // per-step DP barrier (256 threads)
#define BAR_READY(b)  (2 + (b))      // producer -> consumer (384)
#define BAR_FREE(b)   (4 + (b))      // consumer -> producer (384)

__device__ float g_losses[BATCH];
__device__ int   g_cnt = 0;

__device__ __forceinline__ float ex2f(float x) {
    float y; asm("ex2.approx.ftz.f32 %0, %1;" : "=f"(y) : "f"(x)); return y;
}
__device__ __forceinline__ float lg2f(float x) {
    float y; asm("lg2.approx.ftz.f32 %0, %1;" : "=f"(y) : "f"(x)); return y;
}
__device__ __forceinline__ void cp16(void* s, const void* g) {
    unsigned sa = (unsigned)__cvta_generic_to_shared(s);
    asm volatile("cp.async.cg.shared.global [%0], [%1], 16;" :: "r"(sa), "l"(g));
}
__device__ __forceinline__ void bar_sync(int id, int cnt) {
    asm volatile("bar.sync %0, %1;" :: "r"(id), "r"(cnt) : "memory");
}
__device__ __forceinline__ void bar_arrive(int id, int cnt) {
    asm volatile("bar.arrive %0, %1;" :: "r"(id), "r"(cnt) : "memory");
}

// One CTA per batch element. 12 warps: warps 0-7 run the DP in lockstep
// (thread j owns state pair 2j/2j+1), warps 8-11 are producers that stream
// attn rows into a 2-deep chunk ring via cp.async and compute the log-softmax
// denominators. Only 8 boundary odd-alphas cross warps per DP step (smem);
// in-warp neighbors go through shfl_up.
__global__ __launch_bounds__(NTHREADS, 1)
void ctc_kernel(const float* __restrict__ attn,
                const int*   __restrict__ in_lens,
                const int*   __restrict__ out_lens,
                float*       __restrict__ out)
{
    __shared__ __align__(16) float s_chunk[2][CHUNK][TK];
    __shared__ float s_dnb[2][CHUNK];
    __shared__ float s_b[2][8];       // per-warp boundary odd alphas
    __shared__ float s_hi, s_lo;

    const int b    = blockIdx.x;
    const int tid  = threadIdx.x;
    const int lane = tid & 31;
    const int w    = tid >> 5;
    const int L       = in_lens[b];    // 100..200
    const int out_len = out_lens[b];   // 700..900
    const float* attn_b = attn + (size_t)b * TQ * TK;
    const int nchunks = (out_len + CHUNK - 1) / CHUNK;

    if (w >= 8) {
        // ---------------- Producer warps ---------------------------------
        const int ptid = tid - NDP;       // 0..127
        const int pw   = w - 8;           // 0..3
        for (int c = 0; c < nchunks; ++c) {
            const int buf = c & 1;
            if (c >= 2) bar_sync(BAR_FREE(buf), NTHREADS);
            // fill chunk c
            const int t0 = c * CHUNK;
            for (int i = ptid; i < 50 * CHUNK; i += NPROD) {
                int r = i / 50, seg = i % 50;
                int t = t0 + r;
                if (t < out_len)
                    cp16(&s_chunk[buf][r][seg * 4], attn_b + (size_t)t * TK + seg * 4);
            }
            asm volatile("cp.async.commit_group;");
            if (c > 0) {
                asm volatile("cp.async.wait_group 1;");
                // denominators for chunk c-1 (2 rows per producer warp)
                const int pbuf = (c - 1) & 1;
                const int pt0  = (c - 1) * CHUNK;
                #pragma unroll
                for (int rr = 0; rr < 2; ++rr) {
                    int r = pw * 2 + rr;
                    if (pt0 + r < out_len) {
                        float v[7];
                        float m = -1.0f;
                        #pragma unroll
                        for (int i2 = 0; i2 < 7; ++i2) {
                            int k = lane + 32 * i2;
                            v[i2] = (k < TK) ? s_chunk[pbuf][r][k] : NEG;
                            m = fmaxf(m, v[i2]);
                        }
                        #pragma unroll
                        for (int off = 16; off; off >>= 1)
                            m = fmaxf(m, __shfl_xor_sync(0xffffffffu, m, off));
                        float s = 0.f;
                        #pragma unroll
                        for (int i2 = 0; i2 < 7; ++i2) s += ex2f((v[i2] - m) * LOG2E);
                        #pragma unroll
                        for (int off = 16; off; off >>= 1)
                            s += __shfl_xor_sync(0xffffffffu, s, off);
                        s += ex2f((-1.0f - m) * LOG2E);
                        if (lane == 0) s_dnb[pbuf][r] = m * LOG2E + lg2f(s);
                    }
                }
                bar_arrive(BAR_READY(pbuf), NTHREADS);
            }
        }
        // last chunk's denominators
        {
            asm volatile("cp.async.wait_group 0;");
            const int c = nchunks - 1, pbuf = c & 1, pt0 = c * CHUNK;
            #pragma unroll
            for (int rr = 0; rr < 2; ++rr) {
                int r = pw * 2 + rr;
                if (pt0 + r < out_len) {
                    float v[7];
                    float m = -1.0f;
                    #pragma unroll
                    for (int i2 = 0; i2 < 7; ++i2) {
                        int k = lane + 32 * i2;
                        v[i2] = (k < TK) ? s_chunk[pbuf][r][k] : NEG;
                        m = fmaxf(m, v[i2]);
                    }
                    #pragma unroll
                    for (int off = 16; off; off >>= 1)
                        m = fmaxf(m, __shfl_xor_sync(0xffffffffu, m, off));
                    float s = 0.f;
                    #pragma unroll
                    for (int i2 = 0; i2 < 7; ++i2) s += ex2f((v[i2] - m) * LOG2E);
                    #pragma unroll
                    for (int off = 16; off; off >>= 1)
                        s += __shfl_xor_sync(0xffffffffu, s, off);
                    s += ex2f((-1.0f - m) * LOG2E);
                    if (lane == 0) s_dnb[pbuf][r] = m * LOG2E + lg2f(s);
                }
            }
            bar_arrive(BAR_READY(pbuf), NTHREADS);
        }
    } else {
        // ---------------- DP warps (lockstep) -----------------------------
        float a_e = NEG, a_o = NEG;
        int pb = 0;
        const int jx = (tid < TK) ? tid : 0;   // smem column (garbage for j>=200 ok)

        for (int c = 0; c < nchunks; ++c) {
            const int buf = c & 1;
            bar_sync(BAR_READY(buf), NTHREADS);

            // prefetch this chunk's emit logits and denominators into regs
            float x[CHUNK], dnv[CHUNK];
            #pragma unroll
            for (int k = 0; k < CHUNK; ++k) {
                x[k]   = s_chunk[buf][k][jx];
                dnv[k] = s_dnb[buf][k];
            }

            const int t0 = c * CHUNK;
            const int nr = min(CHUNK, out_len - t0);
            #pragma unroll
            for (int k = 0; k < CHUNK; ++k) {
                if (k < nr) {
                    bar_sync(BAR_STEP, NDP);       // publish prev step's s_b
                    const int   t  = t0 + k;
                    const float dn = dnv[k];
                    const float cE = -LOG2E - dn;  // blank emit (log2)

                    float a1 = __shfl_up_sync(0xffffffffu, a_o, 1);
                    if (lane == 0) a1 = (w > 0) ? s_b[pb][w - 1] : NEG;

                    float ne, no;
                    if (t == 0) {
                        ne = (tid == 0) ? cE : NEG;
                        no = (tid == 0) ? (x[0] * LOG2E - dn) : NEG;
                    } else {
                        // q = lse2(a_e, a1); ne = q + cE; no = lse2(a_o, q) + emit
                        float m1 = fmaxf(a_e, a1);
                        float q  = m1 + lg2f(1.0f + ex2f(-fabsf(a_e - a1)));
                        ne = q + cE;
                        float emit = (tid < L) ? (x[k] * LOG2E - dn) : 0.0f;
                        float m2 = fmaxf(a_o, q);
                        no = m2 + lg2f(1.0f + ex2f(-fabsf(a_o - q))) + emit;
                    }
                    if (lane == 31) s_b[pb ^ 1][w] = no;
                    pb ^= 1;
                    a_e = ne; a_o = no;
                }
            }
            bar_arrive(BAR_FREE(buf), NTHREADS);
        }

        if (tid == L)     s_hi = a_e;   // fin[2L]
        if (tid == L - 1) s_lo = a_o;   // fin[2L-1]
    }

    __syncthreads();    // all 384 threads; publishes s_hi/s_lo
    if (tid == 0) {
        float hi = s_hi, lo = s_lo;
        float M  = fmaxf(hi, lo);
        float l2 = M + lg2f(ex2f(hi - M) + ex2f(lo - M));
        float loss = -l2 * LN2;
        if (loss > 1e20f) loss = 0.0f;
        g_losses[b] = loss / (float)L;
        __threadfence();
        int n = atomicAdd(&g_cnt, 1);
        if (n == BATCH - 1) {
            __threadfence();
            float s = 0.f;
            for (int i = 0; i < BATCH; ++i) s += g_losses[i];
            out[0] = s * (1.0f / BATCH);
            g_cnt = 0;               // reset for next (graph-replayed) launch
            __threadfence();
        }
    }
}

extern "C" void kernel_launch(void* const* d_in, const int* in_sizes, int n_in,
                              void* d_out, int out_size)
{
    const float* attn     = (const float*)d_in[0];
    const int*   in_lens  = (const int*)d_in[1];
    const int*   out_lens = (const int*)d_in[2];
    (void)in_sizes; (void)n_in; (void)out_size;

    ctc_kernel<<<BATCH, NTHREADS>>>(attn, in_lens, out_lens, (float*)d_out);
}